// round 8
// baseline (speedup 1.0000x reference)
#include <cuda_runtime.h>
#include <cstdint>
#include <cstddef>

// ============================================================================
// RhythmMemoryUpdater — GB300 sm_103a (base sm_103 target: mma.sync tf32 path)
//   L = 1  =>  out = node_memories; out[node_ids] = LN( x @ W'^T + lin_b )
//   x = [messages | node_memories[node_ids]] (K=256)
//   W'[d,c] = lin_w[d,c] * conv_w[c, period/2]
//
// k_clear/k_mark: byte mask of updated node rows
// k_copy_masked:  high-occupancy copy of non-updated rows
// rhythm_gemm:    persistent 148-CTA, 512-thread GEMM. 16 warps, K split in
//                 halves across warp pairs. x staged as PRE-CONVERTED tf32
//                 bits via LDG.128+STS.128 double buffer (no cp.async, no
//                 read-side cvt). Inner loop: batched LDS.32 -> HMMA only.
// ============================================================================

#define NDIM 128
#define KDIM 256
#define TILE_M 64
#define NTHREADS 512
#define NCTAS 148
#define SX_STRIDE 260            // floats per staged row (1040B, conflict-free)

__device__ uint8_t g_mask[1 << 20];

// ---------------- helpers ----------------
__device__ __forceinline__ uint32_t f2tf32(float f) {
    uint32_t o;
    asm("cvt.rna.tf32.f32 %0, %1;" : "=r"(o) : "f"(f));
    return o;
}
__device__ __forceinline__ void mma_tf32(float c[4], uint32_t a0, uint32_t a1,
                                         uint32_t a2, uint32_t a3,
                                         uint32_t b0, uint32_t b1) {
    asm volatile(
        "mma.sync.aligned.m16n8k8.row.col.f32.tf32.tf32.f32 "
        "{%0,%1,%2,%3}, {%4,%5,%6,%7}, {%8,%9}, {%0,%1,%2,%3};"
        : "+f"(c[0]), "+f"(c[1]), "+f"(c[2]), "+f"(c[3])
        : "r"(a0), "r"(a1), "r"(a2), "r"(a3), "r"(b0), "r"(b1));
}

// ============================================================================
// mask + copy kernels
// ============================================================================
__global__ void __launch_bounds__(256) k_clear(int nbytes16) {
    uint4 z = make_uint4(0, 0, 0, 0);
    uint4* m = (uint4*)g_mask;
    for (int i = blockIdx.x * 256 + threadIdx.x; i < nbytes16; i += gridDim.x * 256)
        m[i] = z;
}
__global__ void __launch_bounds__(256) k_mark(const int* __restrict__ ids, int n) {
    int i = blockIdx.x * 256 + threadIdx.x;
    if (i < n) g_mask[ids[i]] = 1;
}
__global__ void __launch_bounds__(256) k_copy_masked(const float4* __restrict__ src,
                                                     float4* __restrict__ dst,
                                                     int nf4) {
    int stride = gridDim.x * 256;
    for (int i = blockIdx.x * 256 + threadIdx.x; i < nf4; i += stride) {
        int row = i >> 5;
        if (g_mask[row] == 0) dst[i] = src[i];
    }
}

// ============================================================================
// persistent GEMM + LayerNorm + scatter (512 threads, K-split warp pairs)
// ============================================================================
__global__ void __launch_bounds__(NTHREADS, 1) rhythm_gemm(
    const int*   __restrict__ node_ids,
    const float* __restrict__ messages,
    const float* __restrict__ node_mem,
    const float* __restrict__ conv_w,
    const float* __restrict__ lin_w,
    const float* __restrict__ lin_b,
    const float* __restrict__ ln_g,
    const float* __restrict__ ln_bt,
    float*       __restrict__ out,
    int ntiles, int period, int pad)
{
    extern __shared__ uint32_t sX[];              // [2][TILE_M * SX_STRIDE] tf32 bits
    __shared__ float4 s_comb[8 * 8 * 32];         // K-high partials (32 KB)
    __shared__ int    s_node[2][TILE_M];
    __shared__ float2 s_part[8][TILE_M];
    __shared__ float2 s_stats[TILE_M];

    const int tid  = threadIdx.x;
    const int lane = tid & 31;
    const int wid  = tid >> 5;        // 0..15
    const int kh   = wid >> 3;        // K-half: 0 -> k 0..127, 1 -> k 128..255
    const int dblk = wid & 7;         // d block: dblk*16 .. dblk*16+15

    // ---- static per-warp W' fragments (A operand of C^T = W' * x^T) ----
    const int d1 = dblk * 16 + (lane >> 2);
    const int d2 = d1 + 8;
    const int kbase = lane & 3;

    uint32_t areg[16][4];
#pragma unroll
    for (int kt = 0; kt < 16; kt++) {
        int k1 = kh * 128 + kt * 8 + kbase, k2 = k1 + 4;
        float w1 = __ldg(conv_w + k1 * period + pad);
        float w2 = __ldg(conv_w + k2 * period + pad);
        areg[kt][0] = f2tf32(__ldg(lin_w + d1 * KDIM + k1) * w1);
        areg[kt][1] = f2tf32(__ldg(lin_w + d2 * KDIM + k1) * w1);
        areg[kt][2] = f2tf32(__ldg(lin_w + d1 * KDIM + k2) * w2);
        areg[kt][3] = f2tf32(__ldg(lin_w + d2 * KDIM + k2) * w2);
    }
    const float bia1 = __ldg(lin_b + d1), bia2 = __ldg(lin_b + d2);
    const float gm1  = __ldg(ln_g + d1),  gm2  = __ldg(ln_g + d2);
    const float bt1  = __ldg(ln_bt + d1), bt2  = __ldg(ln_bt + d2);

    const float4* msg4 = (const float4*)messages;
    const float4* mem4 = (const float4*)node_mem;

    // ---- staging: 64 rows x 64 float4-chunks; 8 chunks/thread ----
    //      loads  -> regs (coalesced LDG.128), converts to tf32 bits,
    //      stores -> STS.128 straight layout (conflict-free)
    auto stage_loads = [&](int tile, int slot, float4 v[8]) {
#pragma unroll
        for (int i = 0; i < 8; i++) {
            int idx = i * NTHREADS + tid;
            int row = idx >> 6, c = idx & 63;
            long long gr = (long long)tile * TILE_M + row;
            if (c < 32) {
                v[i] = msg4[gr * 32 + c];
            } else {
                int nd = __ldg(node_ids + gr);
                if (c == 32) s_node[slot][row] = nd;
                v[i] = mem4[(long long)nd * 32 + (c - 32)];
            }
        }
    };
    auto stage_stores = [&](int slot, const float4 v[8]) {
        uint32_t* dstS = sX + (size_t)slot * TILE_M * SX_STRIDE;
#pragma unroll
        for (int i = 0; i < 8; i++) {
            int idx = i * NTHREADS + tid;
            int row = idx >> 6, c = idx & 63;
            uint4 o;
            o.x = f2tf32(v[i].x); o.y = f2tf32(v[i].y);
            o.z = f2tf32(v[i].z); o.w = f2tf32(v[i].w);
            *(uint4*)(dstS + row * SX_STRIDE + c * 4) = o;
        }
    };

    // ---- prologue: stage tile 0 into slot 0 ----
    if (blockIdx.x < ntiles) {
        float4 v[8];
        stage_loads(blockIdx.x, 0, v);
        stage_stores(0, v);
    }

    for (int it = 0;; it++) {
        int tile = blockIdx.x + it * gridDim.x;
        if (tile >= ntiles) break;
        const int slot = it & 1;

        __syncthreads();   // staged data in slot visible to all warps

        // ======== MMA: per warp 16 rows(d) x 64 cols(batch), K-half ========
        const uint32_t* xb = sX + (size_t)slot * TILE_M * SX_STRIDE
                           + (lane >> 2) * SX_STRIDE + kh * 128 + kbase;
        float cacc[8][4];
#pragma unroll
        for (int nt = 0; nt < 8; nt++)
#pragma unroll
            for (int j = 0; j < 4; j++) cacc[nt][j] = 0.f;

#pragma unroll
        for (int kt = 0; kt < 16; kt++) {
            uint32_t b[16];
#pragma unroll
            for (int nt = 0; nt < 8; nt++) {
                const uint32_t* xp = xb + nt * 8 * SX_STRIDE + kt * 8;
                b[2 * nt]     = xp[0];
                b[2 * nt + 1] = xp[4];
            }
#pragma unroll
            for (int nt = 0; nt < 8; nt++)
                mma_tf32(cacc[nt], areg[kt][0], areg[kt][1],
                         areg[kt][2], areg[kt][3], b[2 * nt], b[2 * nt + 1]);
        }

        // ---- K-high warps publish partials ----
        if (kh == 1) {
#pragma unroll
            for (int nt = 0; nt < 8; nt++)
                s_comb[(dblk * 8 + nt) * 32 + lane] =
                    make_float4(cacc[nt][0], cacc[nt][1], cacc[nt][2], cacc[nt][3]);
        }
        __syncthreads();   // sX slot reads done + s_comb visible

        // ---- stage next tile: LDG now (latency overlaps epilogue below) ----
        int ntile = tile + gridDim.x;
        float4 v[8];
        if (ntile < ntiles) stage_loads(ntile, slot ^ 1, v);

        // ---- K-low warps: combine + bias + per-row stats ----
        if (kh == 0) {
#pragma unroll
            for (int nt = 0; nt < 8; nt++) {
                float4 p = s_comb[(dblk * 8 + nt) * 32 + lane];
                float vA0 = cacc[nt][0] + p.x + bia1;   // (d1, brA)
                float vA1 = cacc[nt][1] + p.y + bia1;   // (d1, brA+1)
                float vB0 = cacc[nt][2] + p.z + bia2;   // (d2, brA)
                float vB1 = cacc[nt][3] + p.w + bia2;   // (d2, brA+1)
                cacc[nt][0] = vA0; cacc[nt][1] = vA1;
                cacc[nt][2] = vB0; cacc[nt][3] = vB1;
                float s0 = vA0 + vB0, q0 = vA0 * vA0 + vB0 * vB0;
                float s1 = vA1 + vB1, q1 = vA1 * vA1 + vB1 * vB1;
#pragma unroll
                for (int m = 4; m <= 16; m <<= 1) {
                    s0 += __shfl_xor_sync(0xffffffffu, s0, m);
                    q0 += __shfl_xor_sync(0xffffffffu, q0, m);
                    s1 += __shfl_xor_sync(0xffffffffu, s1, m);
                    q1 += __shfl_xor_sync(0xffffffffu, q1, m);
                }
                if (lane < 4) {
                    int brA = nt * 8 + lane * 2;
                    s_part[dblk][brA]     = make_float2(s0, q0);
                    s_part[dblk][brA + 1] = make_float2(s1, q1);
                }
            }
        }
        __syncthreads();

        if (tid < TILE_M) {
            float s = 0.f, q = 0.f;
#pragma unroll
            for (int w = 0; w < 8; w++) {
                float2 p = s_part[w][tid];
                s += p.x; q += p.y;
            }
            float mean = s * (1.0f / 128.0f);
            float var  = q * (1.0f / 128.0f) - mean * mean;
            s_stats[tid] = make_float2(mean, rsqrtf(var + 1e-5f));
        }
        __syncthreads();

        // ---- normalize + scatter (kh0) ; finish staging stores (all) ----
        if (kh == 0) {
#pragma unroll
            for (int nt = 0; nt < 8; nt++) {
                int brA = nt * 8 + (lane & 3) * 2;
                float2 stA = s_stats[brA], stB = s_stats[brA + 1];
                long long ndA = s_node[slot][brA];
                long long ndB = s_node[slot][brA + 1];
                out[ndA * NDIM + d1] = (cacc[nt][0] - stA.x) * stA.y * gm1 + bt1;
                out[ndB * NDIM + d1] = (cacc[nt][1] - stB.x) * stB.y * gm1 + bt1;
                out[ndA * NDIM + d2] = (cacc[nt][2] - stA.x) * stA.y * gm2 + bt2;
                out[ndB * NDIM + d2] = (cacc[nt][3] - stB.x) * stB.y * gm2 + bt2;
            }
        }
        if (ntile < ntiles) stage_stores(slot ^ 1, v);
        // loop-top __syncthreads makes these stores visible before next MMA
    }
}

// ============================================================================
// launch
// ============================================================================
extern "C" void kernel_launch(void* const* d_in, const int* in_sizes, int n_in,
                              void* d_out, int out_size) {
    const int*   node_ids = (const int*)  d_in[0];
    const float* messages = (const float*)d_in[1];
    const float* node_mem = (const float*)d_in[2];
    const float* conv_w   = (const float*)d_in[3];
    const float* lin_w    = (const float*)d_in[4];
    const float* lin_b    = (const float*)d_in[5];
    const float* ln_g     = (const float*)d_in[6];
    const float* ln_bt    = (const float*)d_in[7];
    float* out = (float*)d_out;

    int Btot    = in_sizes[1] / NDIM;            // 262144
    int ntiles  = Btot / TILE_M;                 // 4096
    int period  = in_sizes[3] / KDIM;            // 7
    int pad     = period / 2;                    // 3 (L == 1 path)
    int nf4     = out_size / 4;

    // mask of rows updated by the scatter
    k_clear<<<64, 256>>>((1 << 20) / 16);
    k_mark<<<(Btot + 255) / 256, 256>>>(node_ids, Btot);

    // copy non-updated rows at full occupancy
    k_copy_masked<<<2048, 256>>>((const float4*)node_mem, (float4*)out, nf4);

    // persistent GEMM + LN + scatter
    const int dyn_smem = 2 * TILE_M * SX_STRIDE * 4;   // ~133 KB
    static int configured = -1;
    if (configured != dyn_smem) {
        cudaFuncSetAttribute(rhythm_gemm, cudaFuncAttributeMaxDynamicSharedMemorySize,
                             dyn_smem);
        configured = dyn_smem;
    }
    rhythm_gemm<<<NCTAS, NTHREADS, dyn_smem>>>(node_ids, messages, node_mem, conv_w,
                                               lin_w, lin_b, ln_g, ln_bt, out,
                                               ntiles, period, pad);
}

// round 9
// speedup vs baseline: 1.2248x; 1.2248x over previous
#include <cuda_runtime.h>
#include <cstdint>
#include <cstddef>

// ============================================================================
// RhythmMemoryUpdater — GB300 sm_103a (base sm_103 target: mma.sync tf32 path)
//   L = 1  =>  out = node_memories; out[node_ids] = LN( x @ W'^T + lin_b )
//   x = [messages | node_memories[node_ids]] (K=256)
//   W'[d,c] = lin_w[d,c] * conv_w[c, period/2]
//
// k_clear/k_mark: byte mask of updated node rows
// k_copy_masked:  high-occupancy copy of non-updated rows
// rhythm_gemm:    persistent 148-CTA, 512-thread GEMM. 16 warps, K split in
//                 halves across warp pairs (areg 64 regs/warp), 2-stage
//                 cp.async pipeline. NEW epilogue: combined D staged to smem,
//                 LayerNorm + coalesced scatter by ALL 16 warps.
// ============================================================================

#define NDIM 128
#define KDIM 256
#define TILE_M 64
#define NTHREADS 512
#define NCTAS 148
#define NSLOTS 4                 // node-id ring depth
#define SX_STRIDE 260            // floats per staged x row (1040B)
#define SD_STRIDE 132            // floats per D row (conflict-free: 132%32==4)

__device__ uint8_t g_mask[1 << 20];

// ---------------- helpers ----------------
__device__ __forceinline__ uint32_t smem_u32(const void* p) {
    uint32_t a;
    asm("{ .reg .u64 t; cvta.to.shared.u64 t, %1; cvt.u32.u64 %0, t; }" : "=r"(a) : "l"(p));
    return a;
}
__device__ __forceinline__ uint32_t f2tf32(float f) {
    uint32_t o;
    asm("cvt.rna.tf32.f32 %0, %1;" : "=r"(o) : "f"(f));
    return o;
}
__device__ __forceinline__ void mma_tf32(float c[4], uint32_t a0, uint32_t a1,
                                         uint32_t a2, uint32_t a3,
                                         uint32_t b0, uint32_t b1) {
    asm volatile(
        "mma.sync.aligned.m16n8k8.row.col.f32.tf32.tf32.f32 "
        "{%0,%1,%2,%3}, {%4,%5,%6,%7}, {%8,%9}, {%0,%1,%2,%3};"
        : "+f"(c[0]), "+f"(c[1]), "+f"(c[2]), "+f"(c[3])
        : "r"(a0), "r"(a1), "r"(a2), "r"(a3), "r"(b0), "r"(b1));
}
__device__ __forceinline__ void cp_async16(uint32_t dst, const void* src) {
    asm volatile("cp.async.cg.shared.global [%0], [%1], 16;" :: "r"(dst), "l"(src));
}
#define CP_COMMIT() asm volatile("cp.async.commit_group;" ::: "memory")
#define CP_WAIT1()  asm volatile("cp.async.wait_group 1;" ::: "memory")

// ============================================================================
// mask + copy kernels
// ============================================================================
__global__ void __launch_bounds__(256) k_clear(int nbytes16) {
    uint4 z = make_uint4(0, 0, 0, 0);
    uint4* m = (uint4*)g_mask;
    for (int i = blockIdx.x * 256 + threadIdx.x; i < nbytes16; i += gridDim.x * 256)
        m[i] = z;
}
__global__ void __launch_bounds__(256) k_mark(const int* __restrict__ ids, int n) {
    int i = blockIdx.x * 256 + threadIdx.x;
    if (i < n) g_mask[ids[i]] = 1;
}
__global__ void __launch_bounds__(256) k_copy_masked(const float4* __restrict__ src,
                                                     float4* __restrict__ dst,
                                                     int nf4) {
    int stride = gridDim.x * 256;
    for (int i = blockIdx.x * 256 + threadIdx.x; i < nf4; i += stride) {
        int row = i >> 5;
        if (g_mask[row] == 0) dst[i] = src[i];
    }
}

// ============================================================================
// persistent GEMM + LayerNorm + scatter
// ============================================================================
__global__ void __launch_bounds__(NTHREADS, 1) rhythm_gemm(
    const int*   __restrict__ node_ids,
    const float* __restrict__ messages,
    const float* __restrict__ node_mem,
    const float* __restrict__ conv_w,
    const float* __restrict__ lin_w,
    const float* __restrict__ lin_b,
    const float* __restrict__ ln_g,
    const float* __restrict__ ln_bt,
    float*       __restrict__ out,
    int ntiles, int period, int pad)
{
    // ---- dynamic smem carve ----
    extern __shared__ float dyn[];
    float*  sX     = dyn;                                   // 2*64*260 = 33280 f
    float4* s_comb = (float4*)(dyn + 2 * TILE_M * SX_STRIDE);   // 2048 f4 = 8192 f
    float*  sD     = dyn + 2 * TILE_M * SX_STRIDE + 8192;   // 64*132 = 8448 f
    int*    s_node = (int*)(sD + TILE_M * SD_STRIDE);       // 4*64
    float*  s_gam  = (float*)(s_node + NSLOTS * TILE_M);    // 128
    float*  s_bet  = s_gam + NDIM;                          // 128

    const int tid  = threadIdx.x;
    const int lane = tid & 31;
    const int wid  = tid >> 5;        // 0..15
    const int kh   = wid >> 3;        // K-half
    const int dblk = wid & 7;         // d block

    // ---- static per-warp W' fragments (A operand of C^T = W' * x^T) ----
    const int d1 = dblk * 16 + (lane >> 2);
    const int d2 = d1 + 8;
    const int kbase = lane & 3;

    uint32_t areg[16][4];
#pragma unroll
    for (int kt = 0; kt < 16; kt++) {
        int k1 = kh * 128 + kt * 8 + kbase, k2 = k1 + 4;
        float w1 = __ldg(conv_w + k1 * period + pad);
        float w2 = __ldg(conv_w + k2 * period + pad);
        areg[kt][0] = f2tf32(__ldg(lin_w + d1 * KDIM + k1) * w1);
        areg[kt][1] = f2tf32(__ldg(lin_w + d2 * KDIM + k1) * w1);
        areg[kt][2] = f2tf32(__ldg(lin_w + d1 * KDIM + k2) * w2);
        areg[kt][3] = f2tf32(__ldg(lin_w + d2 * KDIM + k2) * w2);
    }
    const float bia1 = __ldg(lin_b + d1), bia2 = __ldg(lin_b + d2);
    if (tid < NDIM) {
        s_gam[tid] = ln_g[tid];
        s_bet[tid] = ln_bt[tid];
    }

    // ---- cp.async stage: 64 rows x 256 floats ----
    auto stage_tile = [&](int tile, int it_idx) {
        if (tile >= ntiles) return;
        const int dslot = it_idx & 1;
        const int nslot = it_idx & (NSLOTS - 1);
        float* dstS = sX + (size_t)dslot * TILE_M * SX_STRIDE;
#pragma unroll
        for (int i = 0; i < 8; i++) {
            int idx = i * NTHREADS + tid;     // 4096 chunks of 16B
            int row = idx >> 6, c = idx & 63;
            long long gr = (long long)tile * TILE_M + row;
            const float4* src;
            if (c < 32) {
                src = (const float4*)messages + gr * 32 + c;
            } else {
                int nd = __ldg(node_ids + gr);
                if (c == 32) s_node[nslot * TILE_M + row] = nd;
                src = (const float4*)node_mem + (long long)nd * 32 + (c - 32);
            }
            cp_async16(smem_u32(dstS + row * SX_STRIDE + c * 4), src);
        }
    };

    // ---- prologue ----
    stage_tile(blockIdx.x, 0);
    CP_COMMIT();
    stage_tile(blockIdx.x + gridDim.x, 1);
    CP_COMMIT();

    for (int it = 0;; it++) {
        int tile = blockIdx.x + it * gridDim.x;
        if (tile >= ntiles) break;
        const int dslot = it & 1;
        const int nslot = it & (NSLOTS - 1);

        CP_WAIT1();
        __syncthreads();          // staged slot + s_node + (first iter) s_gam

        // ======== MMA: per warp 16 d x 64 batch, K-half ========
        const float* xb = sX + (size_t)dslot * TILE_M * SX_STRIDE
                        + (lane >> 2) * SX_STRIDE + kh * 128 + kbase;
        float cacc[8][4];
#pragma unroll
        for (int nt = 0; nt < 8; nt++)
#pragma unroll
            for (int j = 0; j < 4; j++) cacc[nt][j] = 0.f;

#pragma unroll
        for (int kt = 0; kt < 16; kt++) {
            uint32_t b[16];
#pragma unroll
            for (int nt = 0; nt < 8; nt++) {
                const float* xp = xb + nt * 8 * SX_STRIDE + kt * 8;
                b[2 * nt]     = f2tf32(xp[0]);
                b[2 * nt + 1] = f2tf32(xp[4]);
            }
#pragma unroll
            for (int nt = 0; nt < 8; nt++)
                mma_tf32(cacc[nt], areg[kt][0], areg[kt][1],
                         areg[kt][2], areg[kt][3], b[2 * nt], b[2 * nt + 1]);
        }

        // ---- K-high warps publish partials ----
        if (kh == 1) {
#pragma unroll
            for (int nt = 0; nt < 8; nt++)
                s_comb[(dblk * 8 + nt) * 32 + lane] =
                    make_float4(cacc[nt][0], cacc[nt][1], cacc[nt][2], cacc[nt][3]);
        }
        __syncthreads();          // sX slot free + s_comb visible

        // ---- prefetch tile it+2 into the freed data slot ----
        stage_tile(tile + 2 * gridDim.x, it + 2);
        CP_COMMIT();

        // ---- K-low warps: combine + bias -> sD (conflict-free scalar STS) ----
        if (kh == 0) {
#pragma unroll
            for (int nt = 0; nt < 8; nt++) {
                float4 p = s_comb[(dblk * 8 + nt) * 32 + lane];
                int brA = nt * 8 + (lane & 3) * 2;
                sD[brA * SD_STRIDE + d1]       = cacc[nt][0] + p.x + bia1;
                sD[(brA + 1) * SD_STRIDE + d1] = cacc[nt][1] + p.y + bia1;
                sD[brA * SD_STRIDE + d2]       = cacc[nt][2] + p.z + bia2;
                sD[(brA + 1) * SD_STRIDE + d2] = cacc[nt][3] + p.w + bia2;
            }
        }
        __syncthreads();          // sD complete

        // ---- LayerNorm + coalesced scatter: ALL 512 threads ----
        {
            const int r  = tid >> 3;       // row 0..63
            const int cc = tid & 7;        // f4-chunk base; chunks cc, cc+8, cc+16, cc+24
            float4 v[4];
            float vsum = 0.f, vsq = 0.f;
#pragma unroll
            for (int j = 0; j < 4; j++) {
                v[j] = *(const float4*)&sD[r * SD_STRIDE + (cc + 8 * j) * 4];
                vsum += v[j].x + v[j].y + v[j].z + v[j].w;
                vsq  += v[j].x * v[j].x + v[j].y * v[j].y
                      + v[j].z * v[j].z + v[j].w * v[j].w;
            }
            vsum += __shfl_xor_sync(0xffffffffu, vsum, 1);
            vsq  += __shfl_xor_sync(0xffffffffu, vsq, 1);
            vsum += __shfl_xor_sync(0xffffffffu, vsum, 2);
            vsq  += __shfl_xor_sync(0xffffffffu, vsq, 2);
            vsum += __shfl_xor_sync(0xffffffffu, vsum, 4);
            vsq  += __shfl_xor_sync(0xffffffffu, vsq, 4);
            float mean = vsum * (1.0f / 128.0f);
            float var  = vsq * (1.0f / 128.0f) - mean * mean;
            float rstd = rsqrtf(var + 1e-5f);

            long long nd = s_node[nslot * TILE_M + r];
            float* orow = out + nd * NDIM;
#pragma unroll
            for (int j = 0; j < 4; j++) {
                int cb = (cc + 8 * j) * 4;
                const float4 g = *(const float4*)&s_gam[cb];
                const float4 bt = *(const float4*)&s_bet[cb];
                float4 o;
                o.x = (v[j].x - mean) * rstd * g.x + bt.x;
                o.y = (v[j].y - mean) * rstd * g.y + bt.y;
                o.z = (v[j].z - mean) * rstd * g.z + bt.z;
                o.w = (v[j].w - mean) * rstd * g.w + bt.w;
                *(float4*)&orow[cb] = o;
            }
        }
        // next loop-top __syncthreads protects sD before it is rewritten
    }
}

// ============================================================================
// launch
// ============================================================================
extern "C" void kernel_launch(void* const* d_in, const int* in_sizes, int n_in,
                              void* d_out, int out_size) {
    const int*   node_ids = (const int*)  d_in[0];
    const float* messages = (const float*)d_in[1];
    const float* node_mem = (const float*)d_in[2];
    const float* conv_w   = (const float*)d_in[3];
    const float* lin_w    = (const float*)d_in[4];
    const float* lin_b    = (const float*)d_in[5];
    const float* ln_g     = (const float*)d_in[6];
    const float* ln_bt    = (const float*)d_in[7];
    float* out = (float*)d_out;

    int Btot    = in_sizes[1] / NDIM;            // 262144
    int ntiles  = Btot / TILE_M;                 // 4096
    int period  = in_sizes[3] / KDIM;            // 7
    int pad     = period / 2;                    // 3 (L == 1 path)
    int nf4     = out_size / 4;

    // mask of rows updated by the scatter
    k_clear<<<64, 256>>>((1 << 20) / 16);
    k_mark<<<(Btot + 255) / 256, 256>>>(node_ids, Btot);

    // copy non-updated rows at full occupancy
    k_copy_masked<<<2048, 256>>>((const float4*)node_mem, (float4*)out, nf4);

    // persistent GEMM + LN + scatter
    const int dyn_smem = (2 * TILE_M * SX_STRIDE + 8192 + TILE_M * SD_STRIDE) * 4
                       + NSLOTS * TILE_M * 4 + 2 * NDIM * 4;   // ~202 KB
    static int configured = -1;
    if (configured != dyn_smem) {
        cudaFuncSetAttribute(rhythm_gemm, cudaFuncAttributeMaxDynamicSharedMemorySize,
                             dyn_smem);
        configured = dyn_smem;
    }
    rhythm_gemm<<<NCTAS, NTHREADS, dyn_smem>>>(node_ids, messages, node_mem, conv_w,
                                               lin_w, lin_b, ln_g, ln_bt, out,
                                               ntiles, period, pad);
}